// round 1
// baseline (speedup 1.0000x reference)
#include <cuda_runtime.h>

#define BATCH   4
#define NPTS    4096
#define THREADS 128
#define IPT     2
#define PPB     (THREADS * IPT)        // 256 query points per block
#define TILES   (NPTS / PPB)           // 16 tiles per (batch, direction)
// grid.x = BATCH * 2 * TILES = 128

__device__ float g_acc;

__global__ void zero_acc_kernel() { g_acc = 0.0f; }

__global__ __launch_bounds__(THREADS)
void chamfer_dir_kernel(const float* __restrict__ pred,
                        const float* __restrict__ gt) {
    __shared__ float s[NPTS * 3];      // exactly 49152 bytes

    const int bx   = blockIdx.x;
    const int b    = bx >> 5;          // 32 blocks per batch (2 dirs * 16 tiles)
    const int dir  = (bx >> 4) & 1;
    const int tile = bx & 15;

    const float* src = dir ? gt : pred;    // query points (find NN for these)
    const float* tgt = dir ? pred : gt;    // target cloud (scan in smem)
    src += (size_t)b * NPTS * 3;
    tgt += (size_t)b * NPTS * 3;

    // Cooperative load of full target cloud into smem (float4 vectorized;
    // NPTS*3 = 12288 floats = 3072 float4, 24 per thread).
    {
        const float4* t4 = (const float4*)tgt;
        float4* s4 = (float4*)s;
        #pragma unroll
        for (int i = 0; i < (NPTS * 3 / 4) / THREADS; i++)
            s4[i * THREADS + threadIdx.x] = t4[i * THREADS + threadIdx.x];
    }

    // Register-resident query points
    float px[IPT], py[IPT], pz[IPT], mn[IPT];
    const int base = tile * PPB + threadIdx.x;
    #pragma unroll
    for (int k = 0; k < IPT; k++) {
        const int n = base + k * THREADS;
        px[k] = src[n * 3 + 0];
        py[k] = src[n * 3 + 1];
        pz[k] = src[n * 3 + 2];
        mn[k] = 3.4e38f;
    }
    __syncthreads();

    // Main scan: broadcast LDS of target point, 5 FADD + 1 FMNMX per pair.
    #pragma unroll 8
    for (int m = 0; m < NPTS; m++) {
        const float gx = s[m * 3 + 0];
        const float gy = s[m * 3 + 1];
        const float gz = s[m * 3 + 2];
        #pragma unroll
        for (int k = 0; k < IPT; k++) {
            const float d = fabsf(px[k] - gx)
                          + fabsf(py[k] - gy)
                          + fabsf(pz[k] - gz);
            mn[k] = fminf(mn[k], d);
        }
    }

    // Reduce: thread sum -> warp shuffle -> lane0 atomicAdd (4 atomics/block)
    float v = mn[0] + mn[1];
    #pragma unroll
    for (int o = 16; o; o >>= 1)
        v += __shfl_xor_sync(0xffffffffu, v, o);
    if ((threadIdx.x & 31) == 0)
        atomicAdd(&g_acc, v);
}

__global__ void finalize_kernel(float* __restrict__ out) {
    out[0] = g_acc * (1.0f / ((float)BATCH * (float)NPTS));
}

extern "C" void kernel_launch(void* const* d_in, const int* in_sizes, int n_in,
                              void* d_out, int out_size) {
    const float* pred = (const float*)d_in[0];
    const float* gt   = (const float*)d_in[1];
    float* out = (float*)d_out;
    (void)in_sizes; (void)n_in; (void)out_size;

    zero_acc_kernel<<<1, 1>>>();
    chamfer_dir_kernel<<<BATCH * 2 * TILES, THREADS>>>(pred, gt);
    finalize_kernel<<<1, 1>>>(out);
}

// round 2
// speedup vs baseline: 1.1214x; 1.1214x over previous
#include <cuda_runtime.h>

#define BATCH   4
#define NPTS    4096
#define TS      128          // macro tile (rows x cols)
#define MICRO   8            // per-thread micro tile
#define TDIM    16           // 16x16 threads
#define THREADS (TDIM * TDIM)
#define NBLK    (NPTS / TS)  // 32 tile blocks per dim
#define FINF    0x7F800000u  // +inf as uint (positive floats order as uints)

// [0 .. B*N)       : row mins (nearest gt for each pred point)
// [B*N .. 2*B*N)   : col mins (nearest pred for each gt point)
__device__ unsigned g_min[2 * BATCH * NPTS];

__global__ void init_kernel() {
    int i = blockIdx.x * blockDim.x + threadIdx.x;
    g_min[i] = FINF;
}

__global__ __launch_bounds__(THREADS)
void chamfer_fused_kernel(const float* __restrict__ pred,
                          const float* __restrict__ gt) {
    const int tx = threadIdx.x & (TDIM - 1);
    const int ty = threadIdx.x >> 4;
    const int cblk = blockIdx.x;     // column tile
    const int rblk = blockIdx.y;     // row tile
    const int b    = blockIdx.z;

    __shared__ unsigned scol[TS];
    if (threadIdx.x < TS) scol[threadIdx.x] = FINF;

    const float* prow = pred + (size_t)b * NPTS * 3;
    const float* pcol = gt   + (size_t)b * NPTS * 3;

    const int r0 = rblk * TS + ty * MICRO;
    const int c0 = cblk * TS + tx * MICRO;

    float rx[MICRO], ry[MICRO], rz[MICRO];
    float cx[MICRO], cy[MICRO], cz[MICRO];
    float rmin[MICRO], cmin[MICRO];

    #pragma unroll
    for (int i = 0; i < MICRO; i++) {
        rx[i] = prow[(r0 + i) * 3 + 0];
        ry[i] = prow[(r0 + i) * 3 + 1];
        rz[i] = prow[(r0 + i) * 3 + 2];
        cx[i] = pcol[(c0 + i) * 3 + 0];
        cy[i] = pcol[(c0 + i) * 3 + 1];
        cz[i] = pcol[(c0 + i) * 3 + 2];
        rmin[i] = 3.4e38f;
        cmin[i] = 3.4e38f;
    }
    __syncthreads();   // scol initialized

    // 8x8 micro tile: 64 pairs, each 5 FADD (fma pipe) + 2 FMNMX (alu pipe)
    #pragma unroll
    for (int i = 0; i < MICRO; i++) {
        #pragma unroll
        for (int j = 0; j < MICRO; j++) {
            const float d = fabsf(rx[i] - cx[j])
                          + fabsf(ry[i] - cy[j])
                          + fabsf(rz[i] - cz[j]);
            rmin[i] = fminf(rmin[i], d);
            cmin[j] = fminf(cmin[j], d);
        }
    }

    // Row mins: reduce across tx (contiguous 16 lanes in a half-warp)
    #pragma unroll
    for (int i = 0; i < MICRO; i++) {
        #pragma unroll
        for (int o = 1; o < TDIM; o <<= 1)
            rmin[i] = fminf(rmin[i], __shfl_xor_sync(0xffffffffu, rmin[i], o));
    }
    if (tx == 0) {
        #pragma unroll
        for (int i = 0; i < MICRO; i++)
            atomicMin(&g_min[b * NPTS + r0 + i], __float_as_uint(rmin[i]));
    }

    // Col mins: combine across ty (cross-warp) via smem atomics
    #pragma unroll
    for (int j = 0; j < MICRO; j++)
        atomicMin(&scol[tx * MICRO + j], __float_as_uint(cmin[j]));
    __syncthreads();
    if (threadIdx.x < TS)
        atomicMin(&g_min[BATCH * NPTS + b * NPTS + cblk * TS + threadIdx.x],
                  scol[threadIdx.x]);
}

__global__ __launch_bounds__(1024)
void reduce_kernel(float* __restrict__ out) {
    __shared__ float sw[32];
    float sum = 0.0f;
    for (int i = threadIdx.x; i < 2 * BATCH * NPTS; i += 1024)
        sum += __uint_as_float(g_min[i]);
    #pragma unroll
    for (int o = 16; o; o >>= 1)
        sum += __shfl_xor_sync(0xffffffffu, sum, o);
    if ((threadIdx.x & 31) == 0) sw[threadIdx.x >> 5] = sum;
    __syncthreads();
    if (threadIdx.x < 32) {
        float v = sw[threadIdx.x];
        #pragma unroll
        for (int o = 16; o; o >>= 1)
            v += __shfl_xor_sync(0xffffffffu, v, o);
        if (threadIdx.x == 0)
            out[0] = v * (1.0f / ((float)BATCH * (float)NPTS));
    }
}

extern "C" void kernel_launch(void* const* d_in, const int* in_sizes, int n_in,
                              void* d_out, int out_size) {
    const float* pred = (const float*)d_in[0];
    const float* gt   = (const float*)d_in[1];
    float* out = (float*)d_out;
    (void)in_sizes; (void)n_in; (void)out_size;

    init_kernel<<<(2 * BATCH * NPTS) / 256, 256>>>();
    dim3 grid(NBLK, NBLK, BATCH);
    chamfer_fused_kernel<<<grid, THREADS>>>(pred, gt);
    reduce_kernel<<<1, 1024>>>(out);
}

// round 3
// speedup vs baseline: 1.2382x; 1.1042x over previous
#include <cuda_runtime.h>

#define BATCH   4
#define NPTS    4096
#define TS      128
#define MICRO   8
#define TDIM    16
#define THREADS (TDIM * TDIM)
#define NBLK    (NPTS / TS)   // 32
#define FINF    0x7F800000u

// Partial mins, laid out so each logical "row" has its 32 tile-partials
// contiguous (8x LDG.128 in the reduce kernel):
//  rpart: [b][rblk][row 0..127][cblk 0..31]
//  cpart: [b][cblk][col 0..127][rblk 0..31]   (appended after rpart)
#define HALF   (BATCH * NBLK * TS * NBLK)      // 524288 floats
__device__ float    g_part[2 * HALF];          // 4 MB
__device__ float    g_acc;
__device__ unsigned g_cnt;

// --- FFMA-imm helpers: rt_SMSP=1 vs 2 for FADD/3-reg FFMA ---
__device__ __forceinline__ float fsub1(float a, float b) {   // a - b
    float r;
    asm("fma.rn.f32 %0, %1, 0fBF800000, %2;" : "=f"(r) : "f"(b), "f"(a));
    return r;
}
__device__ __forceinline__ float fadd1(float a, float b) {   // a + b
    float r;
    asm("fma.rn.f32 %0, %1, 0f3F800000, %2;" : "=f"(r) : "f"(a), "f"(b));
    return r;
}

__global__ __launch_bounds__(THREADS)
void chamfer_fused_kernel(const float* __restrict__ pred,
                          const float* __restrict__ gt) {
    const int tx   = threadIdx.x & (TDIM - 1);
    const int ty   = threadIdx.x >> 4;
    const int cblk = blockIdx.x;
    const int rblk = blockIdx.y;
    const int b    = blockIdx.z;

    // Zero the cross-kernel accumulators once per launch (no reader until
    // the reduce kernel; kernel boundary orders visibility).
    if (cblk == 0 && rblk == 0 && b == 0 && threadIdx.x == 0) {
        g_acc = 0.0f;
        g_cnt = 0u;
    }

    __shared__ unsigned scol[TS];
    if (threadIdx.x < TS) scol[threadIdx.x] = FINF;

    const float* prow = pred + (size_t)b * NPTS * 3;
    const float* pcol = gt   + (size_t)b * NPTS * 3;
    const int r0 = rblk * TS + ty * MICRO;
    const int c0 = cblk * TS + tx * MICRO;

    // 8 points = 24 contiguous floats = 6 aligned LDG.128 per side.
    float4 rb4[6], cb4[6];
    {
        const float4* rp = reinterpret_cast<const float4*>(prow + r0 * 3);
        const float4* cp = reinterpret_cast<const float4*>(pcol + c0 * 3);
        #pragma unroll
        for (int i = 0; i < 6; i++) { rb4[i] = rp[i]; cb4[i] = cp[i]; }
    }
    const float* rr = reinterpret_cast<const float*>(rb4);
    const float* cc = reinterpret_cast<const float*>(cb4);

    float rx[MICRO], ry[MICRO], rz[MICRO];
    float cx[MICRO], cy[MICRO], cz[MICRO];
    float rmin[MICRO], cmin[MICRO];
    #pragma unroll
    for (int i = 0; i < MICRO; i++) {
        rx[i] = rr[3 * i]; ry[i] = rr[3 * i + 1]; rz[i] = rr[3 * i + 2];
        cx[i] = cc[3 * i]; cy[i] = cc[3 * i + 1]; cz[i] = cc[3 * i + 2];
        rmin[i] = 3.4e38f;  cmin[i] = 3.4e38f;
    }
    __syncthreads();   // scol ready

    // 64 pairs: 5 FFMA-imm (fma pipe, rt=1) + 2 FMNMX (alu pipe) per pair.
    #pragma unroll
    for (int i = 0; i < MICRO; i++) {
        #pragma unroll
        for (int j = 0; j < MICRO; j++) {
            const float dx = fsub1(rx[i], cx[j]);
            const float dy = fsub1(ry[i], cy[j]);
            const float dz = fsub1(rz[i], cz[j]);
            const float d  = fadd1(fadd1(fabsf(dx), fabsf(dy)), fabsf(dz));
            rmin[i] = fminf(rmin[i], d);
            cmin[j] = fminf(cmin[j], d);
        }
    }

    // Row mins: reduce across tx (lanes with equal ty are xor-1,2,4,8 apart).
    #pragma unroll
    for (int i = 0; i < MICRO; i++) {
        #pragma unroll
        for (int o = 1; o < TDIM; o <<= 1)
            rmin[i] = fminf(rmin[i], __shfl_xor_sync(0xffffffffu, rmin[i], o));
    }
    if (tx == 0) {
        #pragma unroll
        for (int i = 0; i < MICRO; i++)
            g_part[((b * NBLK + rblk) * TS + ty * MICRO + i) * NBLK + cblk]
                = rmin[i];
    }

    // Col mins: combine across ty via smem atomicMin (positive-float==uint order).
    #pragma unroll
    for (int j = 0; j < MICRO; j++)
        atomicMin(&scol[tx * MICRO + j], __float_as_uint(cmin[j]));
    __syncthreads();
    if (threadIdx.x < TS)
        g_part[HALF + ((b * NBLK + cblk) * TS + threadIdx.x) * NBLK + rblk]
            = __uint_as_float(scol[threadIdx.x]);
}

// 32768 logical rows x 32 partials each. 128 blocks x 256 threads: one row
// per thread (8x LDG.128), min-reduce, block-sum, atomicAdd; last block out.
__global__ __launch_bounds__(256)
void reduce_kernel(float* __restrict__ out) {
    __shared__ float sw[8];
    const int row = blockIdx.x * 256 + threadIdx.x;

    const float4* p = reinterpret_cast<const float4*>(&g_part[(size_t)row * NBLK]);
    float mn = 3.4e38f;
    #pragma unroll
    for (int i = 0; i < 8; i++) {
        const float4 v = p[i];
        mn = fminf(mn, fminf(fminf(v.x, v.y), fminf(v.z, v.w)));
    }

    float sum = mn;
    #pragma unroll
    for (int o = 16; o; o >>= 1)
        sum += __shfl_xor_sync(0xffffffffu, sum, o);
    if ((threadIdx.x & 31) == 0) sw[threadIdx.x >> 5] = sum;
    __syncthreads();

    if (threadIdx.x == 0) {
        float v = 0.0f;
        #pragma unroll
        for (int w = 0; w < 8; w++) v += sw[w];
        atomicAdd(&g_acc, v);
        __threadfence();
        const unsigned ticket = atomicAdd(&g_cnt, 1u);
        if (ticket == 127u) {
            const float total = atomicAdd(&g_acc, 0.0f);  // L2-coherent read
            out[0] = total * (1.0f / ((float)BATCH * (float)NPTS));
        }
    }
}

extern "C" void kernel_launch(void* const* d_in, const int* in_sizes, int n_in,
                              void* d_out, int out_size) {
    const float* pred = (const float*)d_in[0];
    const float* gt   = (const float*)d_in[1];
    float* out = (float*)d_out;
    (void)in_sizes; (void)n_in; (void)out_size;

    dim3 grid(NBLK, NBLK, BATCH);
    chamfer_fused_kernel<<<grid, THREADS>>>(pred, gt);
    reduce_kernel<<<128, 256>>>(out);
}

// round 4
// speedup vs baseline: 1.3992x; 1.1300x over previous
#include <cuda_runtime.h>

#define BATCH   4
#define NPTS    4096
#define TS      128
#define MICRO   8
#define TDIM    16
#define THREADS (TDIM * TDIM)
#define NBLK    (NPTS / TS)   // 32

// Partials: each logical row has its 32 tile-partials contiguous.
//  rpart: [b][rblk][row 0..127][cblk 0..31]
//  cpart: [b][cblk][col 0..127][rblk 0..31]
#define HALF   (BATCH * NBLK * TS * NBLK)      // 524288 floats
__device__ float    g_part[2 * HALF];          // 4 MB
__device__ float    g_acc;
__device__ unsigned g_cnt;

// FFMA-imm helpers: rt_SMSP=1 (vs 2 for FADD / 3-reg FFMA)
__device__ __forceinline__ float fsub1(float a, float b) {   // a - b
    float r;
    asm("fma.rn.f32 %0, %1, 0fBF800000, %2;" : "=f"(r) : "f"(b), "f"(a));
    return r;
}
__device__ __forceinline__ float fadd1(float a, float b) {   // a + b
    float r;
    asm("fma.rn.f32 %0, %1, 0f3F800000, %2;" : "=f"(r) : "f"(a), "f"(b));
    return r;
}

__global__ __launch_bounds__(THREADS)
void chamfer_fused_kernel(const float* __restrict__ pred,
                          const float* __restrict__ gt) {
    const int tx   = threadIdx.x & (TDIM - 1);
    const int ty   = threadIdx.x >> 4;
    const int cblk = blockIdx.x;
    const int rblk = blockIdx.y;
    const int b    = blockIdx.z;

    // Zero cross-kernel accumulators (no reader until the reduce launch).
    if (cblk == 0 && rblk == 0 && b == 0 && threadIdx.x == 0) {
        g_acc = 0.0f;
        g_cnt = 0u;
    }

    __shared__ float swcol[8][TS];   // per-warp col-min partials (no atomics)

    const float* prow = pred + (size_t)b * NPTS * 3;
    const float* pcol = gt   + (size_t)b * NPTS * 3;
    const int r0 = rblk * TS + ty * MICRO;
    const int c0 = cblk * TS + tx * MICRO;

    // 8 points = 24 contiguous floats = 6 aligned LDG.128 per side.
    float4 rb4[6], cb4[6];
    {
        const float4* rp = reinterpret_cast<const float4*>(prow + r0 * 3);
        const float4* cp = reinterpret_cast<const float4*>(pcol + c0 * 3);
        #pragma unroll
        for (int i = 0; i < 6; i++) { rb4[i] = rp[i]; cb4[i] = cp[i]; }
    }
    const float* rr = reinterpret_cast<const float*>(rb4);
    const float* cc = reinterpret_cast<const float*>(cb4);

    float rx[MICRO], ry[MICRO], rz[MICRO];
    float cx[MICRO], cy[MICRO], cz[MICRO];
    float rmin[MICRO], cmin[MICRO];
    #pragma unroll
    for (int i = 0; i < MICRO; i++) {
        rx[i] = rr[3 * i]; ry[i] = rr[3 * i + 1]; rz[i] = rr[3 * i + 2];
        cx[i] = cc[3 * i]; cy[i] = cc[3 * i + 1]; cz[i] = cc[3 * i + 2];
        rmin[i] = 3.4e38f;  cmin[i] = 3.4e38f;
    }

    // 64 pairs: 5 FFMA-imm (fma pipe) + 2 FMNMX (alu pipe) per pair.
    #pragma unroll
    for (int i = 0; i < MICRO; i++) {
        #pragma unroll
        for (int j = 0; j < MICRO; j++) {
            const float dx = fsub1(rx[i], cx[j]);
            const float dy = fsub1(ry[i], cy[j]);
            const float dz = fsub1(rz[i], cz[j]);
            const float d  = fadd1(fadd1(fabsf(dx), fabsf(dy)), fabsf(dz));
            rmin[i] = fminf(rmin[i], d);
            cmin[j] = fminf(cmin[j], d);
        }
    }

    // Row mins: xor-shuffle across the 16 tx lanes (stays inside ty group).
    #pragma unroll
    for (int i = 0; i < MICRO; i++) {
        #pragma unroll
        for (int o = 1; o < TDIM; o <<= 1)
            rmin[i] = fminf(rmin[i], __shfl_xor_sync(0xffffffffu, rmin[i], o));
    }
    if (tx == 0) {
        #pragma unroll
        for (int i = 0; i < MICRO; i++)
            g_part[((b * NBLK + rblk) * TS + ty * MICRO + i) * NBLK + cblk]
                = rmin[i];
    }

    // Col mins, atomic-free: fold the warp's two ty values via xor-16,
    // lanes 0..15 store their 8 col-partials (plain STS), then 128 threads
    // min across the 8 warps (conflict-free LDS) and store to gmem.
    const int warp = threadIdx.x >> 5;
    const int lane = threadIdx.x & 31;
    #pragma unroll
    for (int j = 0; j < MICRO; j++)
        cmin[j] = fminf(cmin[j], __shfl_xor_sync(0xffffffffu, cmin[j], 16));
    if (lane < 16) {
        #pragma unroll
        for (int j = 0; j < MICRO; j++)
            swcol[warp][lane * MICRO + j] = cmin[j];
    }
    __syncthreads();
    if (threadIdx.x < TS) {
        float m = swcol[0][threadIdx.x];
        #pragma unroll
        for (int w = 1; w < 8; w++)
            m = fminf(m, swcol[w][threadIdx.x]);
        g_part[HALF + ((b * NBLK + cblk) * TS + threadIdx.x) * NBLK + rblk] = m;
    }
}

// 32768 logical rows x 32 partials. 2 threads per row (4x LDG.128 each),
// fold halves via xor-1 shuffle, each lane contributes half the row min.
__global__ __launch_bounds__(256)
void reduce_kernel(float* __restrict__ out) {
    __shared__ float sw[8];
    const int t = blockIdx.x * 256 + threadIdx.x;     // 65536 threads

    const float4* p = reinterpret_cast<const float4*>(&g_part[(size_t)t * 16]);
    float mn = 3.4e38f;
    #pragma unroll
    for (int i = 0; i < 4; i++) {
        const float4 v = p[i];
        mn = fminf(mn, fminf(fminf(v.x, v.y), fminf(v.z, v.w)));
    }
    mn = fminf(mn, __shfl_xor_sync(0xffffffffu, mn, 1));  // full row min
    float sum = mn * 0.5f;                                // both lanes count half

    #pragma unroll
    for (int o = 16; o; o >>= 1)
        sum += __shfl_xor_sync(0xffffffffu, sum, o);
    if ((threadIdx.x & 31) == 0) sw[threadIdx.x >> 5] = sum;
    __syncthreads();

    if (threadIdx.x == 0) {
        float v = 0.0f;
        #pragma unroll
        for (int w = 0; w < 8; w++) v += sw[w];
        atomicAdd(&g_acc, v);
        __threadfence();
        const unsigned ticket = atomicAdd(&g_cnt, 1u);
        if (ticket == 255u) {
            const float total = atomicAdd(&g_acc, 0.0f);  // coherent read
            out[0] = total * (1.0f / ((float)BATCH * (float)NPTS));
        }
    }
}

extern "C" void kernel_launch(void* const* d_in, const int* in_sizes, int n_in,
                              void* d_out, int out_size) {
    const float* pred = (const float*)d_in[0];
    const float* gt   = (const float*)d_in[1];
    float* out = (float*)d_out;
    (void)in_sizes; (void)n_in; (void)out_size;

    dim3 grid(NBLK, NBLK, BATCH);
    chamfer_fused_kernel<<<grid, THREADS>>>(pred, gt);
    reduce_kernel<<<256, 256>>>(out);
}

// round 5
// speedup vs baseline: 1.4021x; 1.0021x over previous
#include <cuda_runtime.h>

#define BATCH   4
#define NPTS    4096
#define TS      128
#define MICRO   8
#define TDIM    16
#define THREADS (TDIM * TDIM)
#define NBLK    (NPTS / TS)   // 32

// Partials: each logical row has its 32 tile-partials contiguous.
//  rpart: [b][rblk][row 0..127][cblk 0..31]
//  cpart: [b][cblk][col 0..127][rblk 0..31]
#define HALF   (BATCH * NBLK * TS * NBLK)      // 524288 floats
#define NPART  (2 * HALF)                       // 1M floats = 4 MB
__device__ float    g_part[NPART];
__device__ float    g_acc;
__device__ unsigned g_cnt;

// FFMA-imm subtract: rt_SMSP=1 (vs 2 for FADD). Abs is NOT foldable into
// FFMA, so sums are done in plain C (FADD with |src| operand modifiers).
__device__ __forceinline__ float fsub1(float a, float b) {   // a - b
    float r;
    asm("fma.rn.f32 %0, %1, 0fBF800000, %2;" : "=f"(r) : "f"(b), "f"(a));
    return r;
}

__global__ __launch_bounds__(THREADS)
void chamfer_fused_kernel(const float* __restrict__ pred,
                          const float* __restrict__ gt) {
    const int tx   = threadIdx.x & (TDIM - 1);
    const int ty   = threadIdx.x >> 4;
    const int cblk = blockIdx.x;
    const int rblk = blockIdx.y;
    const int b    = blockIdx.z;

    // Zero cross-kernel accumulators (no reader until the reduce launch).
    if (cblk == 0 && rblk == 0 && b == 0 && threadIdx.x == 0) {
        g_acc = 0.0f;
        g_cnt = 0u;
    }

    __shared__ float swcol[8][TS];   // per-warp col-min partials (no atomics)

    const float* prow = pred + (size_t)b * NPTS * 3;
    const float* pcol = gt   + (size_t)b * NPTS * 3;
    const int r0 = rblk * TS + ty * MICRO;
    const int c0 = cblk * TS + tx * MICRO;

    // 8 points = 24 contiguous floats = 6 aligned LDG.128 per side.
    float4 rb4[6], cb4[6];
    {
        const float4* rp = reinterpret_cast<const float4*>(prow + r0 * 3);
        const float4* cp = reinterpret_cast<const float4*>(pcol + c0 * 3);
        #pragma unroll
        for (int i = 0; i < 6; i++) { rb4[i] = rp[i]; cb4[i] = cp[i]; }
    }
    const float* rr = reinterpret_cast<const float*>(rb4);
    const float* cc = reinterpret_cast<const float*>(cb4);

    float rx[MICRO], ry[MICRO], rz[MICRO];
    float cx[MICRO], cy[MICRO], cz[MICRO];
    float rmin[MICRO], cmin[MICRO];
    #pragma unroll
    for (int i = 0; i < MICRO; i++) {
        rx[i] = rr[3 * i]; ry[i] = rr[3 * i + 1]; rz[i] = rr[3 * i + 2];
        cx[i] = cc[3 * i]; cy[i] = cc[3 * i + 1]; cz[i] = cc[3 * i + 2];
        rmin[i] = 3.4e38f;  cmin[i] = 3.4e38f;
    }

    // 64 pairs: 3 FFMA-imm (fma rt1) + 2 FADD w/ folded |.| (fma rt2)
    //         + 2 FMNMX (alu rt2).  fma=7cyc, alu=4cyc, issue=7 per pair.
    #pragma unroll
    for (int i = 0; i < MICRO; i++) {
        #pragma unroll
        for (int j = 0; j < MICRO; j++) {
            const float dx = fsub1(rx[i], cx[j]);
            const float dy = fsub1(ry[i], cy[j]);
            const float dz = fsub1(rz[i], cz[j]);
            const float d  = (fabsf(dx) + fabsf(dy)) + fabsf(dz);
            rmin[i] = fminf(rmin[i], d);
            cmin[j] = fminf(cmin[j], d);
        }
    }

    // Row mins: xor-shuffle across the 16 tx lanes.
    #pragma unroll
    for (int i = 0; i < MICRO; i++) {
        #pragma unroll
        for (int o = 1; o < TDIM; o <<= 1)
            rmin[i] = fminf(rmin[i], __shfl_xor_sync(0xffffffffu, rmin[i], o));
    }
    if (tx == 0) {
        #pragma unroll
        for (int i = 0; i < MICRO; i++)
            g_part[((b * NBLK + rblk) * TS + ty * MICRO + i) * NBLK + cblk]
                = rmin[i];
    }

    // Col mins, atomic-free: xor-16 fold, lanes<16 STS, min across 8 warps.
    const int warp = threadIdx.x >> 5;
    const int lane = threadIdx.x & 31;
    #pragma unroll
    for (int j = 0; j < MICRO; j++)
        cmin[j] = fminf(cmin[j], __shfl_xor_sync(0xffffffffu, cmin[j], 16));
    if (lane < 16) {
        #pragma unroll
        for (int j = 0; j < MICRO; j++)
            swcol[warp][lane * MICRO + j] = cmin[j];
    }
    __syncthreads();
    if (threadIdx.x < TS) {
        float m = swcol[0][threadIdx.x];
        #pragma unroll
        for (int w = 1; w < 8; w++)
            m = fminf(m, swcol[w][threadIdx.x]);
        g_part[HALF + ((b * NBLK + cblk) * TS + threadIdx.x) * NBLK + rblk] = m;
    }
}

// 262144 threads, ONE LDG.128 each (max MLP, BW-bound). A logical row's 32
// partials = 8 consecutive float4 = 8 adjacent lanes; 3 xor-shuffles fold to
// the row min in all 8 lanes, each contributes rowmin/8 to the sum.
__global__ __launch_bounds__(256)
void reduce_kernel(float* __restrict__ out) {
    __shared__ float sw[8];
    const int t = blockIdx.x * 256 + threadIdx.x;   // 0 .. NPART/4

    const float4 v = reinterpret_cast<const float4*>(g_part)[t];
    float m = fminf(fminf(v.x, v.y), fminf(v.z, v.w));
    #pragma unroll
    for (int o = 1; o < 8; o <<= 1)
        m = fminf(m, __shfl_xor_sync(0xffffffffu, m, o));
    float sum = m * 0.125f;   // 8 lanes each contribute 1/8 of the row min

    #pragma unroll
    for (int o = 16; o; o >>= 1)
        sum += __shfl_xor_sync(0xffffffffu, sum, o);
    if ((threadIdx.x & 31) == 0) sw[threadIdx.x >> 5] = sum;
    __syncthreads();

    if (threadIdx.x == 0) {
        float v2 = 0.0f;
        #pragma unroll
        for (int w = 0; w < 8; w++) v2 += sw[w];
        atomicAdd(&g_acc, v2);
        __threadfence();
        const unsigned ticket = atomicAdd(&g_cnt, 1u);
        if (ticket == (NPART / 4 / 256) - 1) {
            const float total = atomicAdd(&g_acc, 0.0f);  // coherent read
            out[0] = total * (1.0f / ((float)BATCH * (float)NPTS));
        }
    }
}

extern "C" void kernel_launch(void* const* d_in, const int* in_sizes, int n_in,
                              void* d_out, int out_size) {
    const float* pred = (const float*)d_in[0];
    const float* gt   = (const float*)d_in[1];
    float* out = (float*)d_out;
    (void)in_sizes; (void)n_in; (void)out_size;

    dim3 grid(NBLK, NBLK, BATCH);
    chamfer_fused_kernel<<<grid, THREADS>>>(pred, gt);
    reduce_kernel<<<NPART / 4 / 256, 256>>>(out);
}

// round 6
// speedup vs baseline: 1.5767x; 1.1246x over previous
#include <cuda_runtime.h>

#define BATCH   4
#define NPTS    4096
#define TS      128
#define MICRO   8
#define TDIM    16
#define THREADS (TDIM * TDIM)
#define NBLK    (NPTS / TS)      // 32 tiles per dim
#define CTPB    4                // col tiles per block
#define CGRPS   (NBLK / CTPB)    // 8
#define HALFK   (BATCH * NPTS)   // 16384
#define NKEY    (2 * HALFK)      // 32768 keys = 128 KB

// Bit-inverted distance keys: key = ~bits(d), d>=0  =>  max(key) == min(d),
// and every valid key > 0, so ZERO-initialized memory is the identity.
// Statics are zero-initialized; reduce_kernel restores zeros after reading,
// so every graph replay starts clean. No init kernel.
__device__ unsigned g_key[NKEY];
__device__ float    g_acc;       // zero-init; reset by reduce_kernel
__device__ unsigned g_cnt;

// FFMA-imm subtract: rt_SMSP=1
__device__ __forceinline__ float fsub1(float a, float b) {   // a - b
    float r;
    asm("fma.rn.f32 %0, %1, 0fBF800000, %2;" : "=f"(r) : "f"(b), "f"(a));
    return r;
}

__global__ __launch_bounds__(THREADS)
void chamfer_fused_kernel(const float* __restrict__ pred,
                          const float* __restrict__ gt) {
    const int tx   = threadIdx.x & (TDIM - 1);
    const int ty   = threadIdx.x >> 4;
    const int cgrp = blockIdx.x;          // 0..7  (4 col tiles each)
    const int rblk = blockIdx.y;          // 0..31
    const int b    = blockIdx.z;

    __shared__ float swcol[8][TS];

    const float* prow = pred + (size_t)b * NPTS * 3;
    const float* pcol = gt   + (size_t)b * NPTS * 3;
    const int r0 = rblk * TS + ty * MICRO;

    // Row coords: 8 points = 24 floats = 6 aligned LDG.128 (persist all tiles)
    float4 rb4[6];
    {
        const float4* rp = reinterpret_cast<const float4*>(prow + r0 * 3);
        #pragma unroll
        for (int i = 0; i < 6; i++) rb4[i] = rp[i];
    }
    const float* rr = reinterpret_cast<const float*>(rb4);
    float rx[MICRO], ry[MICRO], rz[MICRO], rmin[MICRO];
    #pragma unroll
    for (int i = 0; i < MICRO; i++) {
        rx[i] = rr[3 * i]; ry[i] = rr[3 * i + 1]; rz[i] = rr[3 * i + 2];
        rmin[i] = 3.4e38f;
    }

    const int warp = threadIdx.x >> 5;
    const int lane = threadIdx.x & 31;

    for (int t = 0; t < CTPB; t++) {
        const int cbase = (cgrp * CTPB + t) * TS;
        const int c0 = cbase + tx * MICRO;

        float4 cb4[6];
        {
            const float4* cp = reinterpret_cast<const float4*>(pcol + c0 * 3);
            #pragma unroll
            for (int i = 0; i < 6; i++) cb4[i] = cp[i];
        }
        const float* cc = reinterpret_cast<const float*>(cb4);
        float cx[MICRO], cy[MICRO], cz[MICRO], cmin[MICRO];
        #pragma unroll
        for (int j = 0; j < MICRO; j++) {
            cx[j] = cc[3 * j]; cy[j] = cc[3 * j + 1]; cz[j] = cc[3 * j + 2];
            cmin[j] = 3.4e38f;
        }

        // 64 pairs: 3 FFMA-imm + 2 FADD(|.| folded) + 2 FMNMX
        #pragma unroll
        for (int i = 0; i < MICRO; i++) {
            #pragma unroll
            for (int j = 0; j < MICRO; j++) {
                const float dx = fsub1(rx[i], cx[j]);
                const float dy = fsub1(ry[i], cy[j]);
                const float dz = fsub1(rz[i], cz[j]);
                const float d  = (fabsf(dx) + fabsf(dy)) + fabsf(dz);
                rmin[i] = fminf(rmin[i], d);
                cmin[j] = fminf(cmin[j], d);
            }
        }

        // Col epilogue: xor16 fold, lanes<16 STS, min across warps, REDG.MAX.
        #pragma unroll
        for (int j = 0; j < MICRO; j++)
            cmin[j] = fminf(cmin[j], __shfl_xor_sync(0xffffffffu, cmin[j], 16));
        if (lane < 16) {
            #pragma unroll
            for (int j = 0; j < MICRO; j++)
                swcol[warp][lane * MICRO + j] = cmin[j];
        }
        __syncthreads();
        if (threadIdx.x < TS) {
            float m = swcol[0][threadIdx.x];
            #pragma unroll
            for (int w = 1; w < 8; w++)
                m = fminf(m, swcol[w][threadIdx.x]);
            atomicMax(&g_key[HALFK + b * NPTS + cbase + threadIdx.x],
                      ~__float_as_uint(m));
        }
        __syncthreads();   // swcol reuse next tile
    }

    // Row epilogue (once): fold across the 16 tx lanes, tx==0 publishes.
    #pragma unroll
    for (int i = 0; i < MICRO; i++) {
        #pragma unroll
        for (int o = 1; o < TDIM; o <<= 1)
            rmin[i] = fminf(rmin[i], __shfl_xor_sync(0xffffffffu, rmin[i], o));
    }
    if (tx == 0) {
        #pragma unroll
        for (int i = 0; i < MICRO; i++)
            atomicMax(&g_key[b * NPTS + r0 + i], ~__float_as_uint(rmin[i]));
    }
}

// 32 blocks x 256 threads; each thread: 4 keys (1 LDG.128), flip+sum,
// restore zeros, block atomicAdd, last ticket finalizes + resets state.
__global__ __launch_bounds__(256)
void reduce_kernel(float* __restrict__ out) {
    __shared__ float sw[8];
    const int t = blockIdx.x * 256 + threadIdx.x;     // 0..8191

    uint4* p = reinterpret_cast<uint4*>(g_key) + t;
    const uint4 k = *p;
    *p = make_uint4(0u, 0u, 0u, 0u);                  // restore identity

    float sum = __uint_as_float(~k.x) + __uint_as_float(~k.y)
              + __uint_as_float(~k.z) + __uint_as_float(~k.w);

    #pragma unroll
    for (int o = 16; o; o >>= 1)
        sum += __shfl_xor_sync(0xffffffffu, sum, o);
    if ((threadIdx.x & 31) == 0) sw[threadIdx.x >> 5] = sum;
    __syncthreads();

    if (threadIdx.x == 0) {
        float v = 0.0f;
        #pragma unroll
        for (int w = 0; w < 8; w++) v += sw[w];
        atomicAdd(&g_acc, v);
        __threadfence();
        const unsigned ticket = atomicAdd(&g_cnt, 1u);
        if (ticket == 31u) {
            const float total = atomicAdd(&g_acc, 0.0f);  // coherent read
            out[0] = total * (1.0f / ((float)BATCH * (float)NPTS));
            __threadfence();
            g_acc = 0.0f;     // reset for next graph replay
            g_cnt = 0u;
        }
    }
}

extern "C" void kernel_launch(void* const* d_in, const int* in_sizes, int n_in,
                              void* d_out, int out_size) {
    const float* pred = (const float*)d_in[0];
    const float* gt   = (const float*)d_in[1];
    float* out = (float*)d_out;
    (void)in_sizes; (void)n_in; (void)out_size;

    dim3 grid(CGRPS, NBLK, BATCH);    // 8 x 32 x 4 = 1024 blocks
    chamfer_fused_kernel<<<grid, THREADS>>>(pred, gt);
    reduce_kernel<<<NKEY / 4 / 256, 256>>>(out);
}